// round 15
// baseline (speedup 1.0000x reference)
#include <cuda_runtime.h>
#include <cuda_fp16.h>
#include <math.h>
#include <cstdint>

namespace {
constexpr int NB = 72;
constexpr int SS = 512;
constexpr int HH = 768;
constexpr int NG = 8;
constexpr int SN = 9;
constexpr float TEMP_ = 0.07f;
constexpr float AVG_EPS_ = 1e-6f;
constexpr float COS_EPS_ = 1e-8f;
constexpr int VR = 2;
constexpr int SPLITS = 8;
constexpr int SCHUNK = SS / SPLITS;  // 64

constexpr int TM = 128, TN = 128, KC = 64;
constexpr int NCHUNK = HH / KC;  // 12

// smem layout (dynamic, 72192 B)
constexpr int SM_TURNT = 0;
constexpr int SM_TURNS = 512;
constexpr int SM_WQT   = 1024;
constexpr int SM_WAT   = 1536;
constexpr int SM_WNT   = 2048;
constexpr int SM_MQS   = 2560;
constexpr int SM_MAS   = 3072;
constexpr int SM_MNS   = 3584;
constexpr int SM_SWQ   = 4096;
constexpr int SM_SWA   = 4608;
constexpr int SM_SWN   = 5120;
constexpr int SM_STAGE = 6144;
constexpr int STAGE_BYTES = 32768;
constexpr int A_HI = 0, B_HI = 16384;
constexpr int WSTRIDE = 129;
constexpr int SMEM_BYTES = SM_STAGE + 128 * WSTRIDE * 4;  // 72192

constexpr int GRID = 296;          // 2 CTAs/SM * 148 SMs; all co-resident
constexpr int NTILE_JOBS = NB * 10;   // 720
constexpr int NCHUNK_JOBS = NB * SPLITS;  // 576
}

// Scratch
__device__ float g_mask[3][NB * SS];
__device__ float g_msum[3][NB];
__device__ float g_self[3][NB * HH];
__device__ float g_alpha[3][NB * SS];
__device__ float g_cross[3][NB * HH];
__device__ float g_logits[3][NB];

// Sync state: [0,72) mask_ready, [72,144) tiles_done, [144,216) chunks_done,
//             [216] logits_done, [217] next_tile, [218] next_chunk
__device__ int g_sync[219];

__device__ __constant__ int cTI[10] = {0,0,0,0,1,1,1,2,2,3};
__device__ __constant__ int cTJ[10] = {0,1,2,3,1,2,3,2,3,3};

// ===================== helpers =====================
__device__ __forceinline__ uint32_t smem_u32(const void* p) {
    uint32_t a;
    asm("{ .reg .u64 t; cvta.to.shared.u64 t, %1; cvt.u32.u64 %0, t; }" : "=r"(a) : "l"(p));
    return a;
}
__device__ __forceinline__ uint32_t swz128(uint32_t off) { return off ^ ((off >> 3) & 0x70); }

__device__ __forceinline__ void ldmx4(uint32_t* r, uint32_t addr) {
    asm volatile("ldmatrix.sync.aligned.m8n8.x4.shared.b16 {%0,%1,%2,%3}, [%4];"
                 : "=r"(r[0]), "=r"(r[1]), "=r"(r[2]), "=r"(r[3]) : "r"(addr));
}
__device__ __forceinline__ void mma16816(float* d, const uint32_t* a, const uint32_t* b) {
    asm volatile(
        "mma.sync.aligned.m16n8k16.row.col.f32.f16.f16.f32 "
        "{%0,%1,%2,%3}, {%4,%5,%6,%7}, {%8,%9}, {%0,%1,%2,%3};"
        : "+f"(d[0]), "+f"(d[1]), "+f"(d[2]), "+f"(d[3])
        : "r"(a[0]), "r"(a[1]), "r"(a[2]), "r"(a[3]), "r"(b[0]), "r"(b[1]));
}
__device__ __forceinline__ uint32_t h2u(__half2 h) {
    return *reinterpret_cast<uint32_t*>(&h);
}
__device__ __forceinline__ void cvt_store_hi(char* stgp, int base, uint32_t off,
                                             const float4& v0, const float4& v1) {
    uint4 Hi;
    Hi.x = h2u(__floats2half2_rn(v0.x, v0.y));
    Hi.y = h2u(__floats2half2_rn(v0.z, v0.w));
    Hi.z = h2u(__floats2half2_rn(v1.x, v1.y));
    Hi.w = h2u(__floats2half2_rn(v1.z, v1.w));
    *(uint4*)(stgp + base + off) = Hi;
}

// signal: every thread fences its writes, barrier, tid0 bumps counter
#define SIGNAL(ctr) do { __threadfence(); __syncthreads(); \
    if (tid == 0) atomicAdd((ctr), 1); } while (0)
// wait: tid0 spins (acquire via atomic), barrier releases the block
#define WAITC(ctr, tgt) do { if (tid == 0) { \
    while (atomicAdd((ctr), 0) < (tgt)) __nanosleep(128); __threadfence(); } \
    __syncthreads(); } while (0)

// ---------------------------------------------------------------------------
__global__ void k_reset() {
    int i = threadIdx.x;
    if (i < 219) g_sync[i] = 0;
}

// ---------------------------------------------------------------------------
__global__ void __launch_bounds__(256, 2)
k_persist(const float* __restrict__ x,
          const float* __restrict__ am,
          const int* __restrict__ qa,
          const int* __restrict__ turn,
          const float* __restrict__ labels,
          float* __restrict__ out) {
    extern __shared__ char smem[];
    const uint32_t sb = smem_u32(smem);
    const int tid = threadIdx.x, bid = blockIdx.x;
    const int wid = tid >> 5, lane = tid & 31;
    int* mask_ready  = g_sync;
    int* tiles_done  = g_sync + 72;
    int* chunks_done = g_sync + 144;
    int* logits_done = g_sync + 216;
    int* next_tile   = g_sync + 217;
    int* next_chunk  = g_sync + 218;
    __shared__ int s_job;

    // ===================== Phase A: masks + msum + zero (blocks 0..71) ====
    if (bid < NB) {
        const int b = bid;
        float* redA = (float*)smem;  // 3*8 floats
        float pq = 0.f, pa = 0.f, pn = 0.f;
        for (int s = tid; s < SS; s += 256) {
            int q = qa[b * SS + s];
            float a = am[b * SS + s];
            float mq = (q == 1 || q == 2) ? a : 0.f;
            float ma = (q == 0 || q == 2) ? a : 0.f;
            float mn = (q == 3) ? a : 0.f;
            g_mask[0][b * SS + s] = mq;
            g_mask[1][b * SS + s] = ma;
            g_mask[2][b * SS + s] = mn;
            g_alpha[0][b * SS + s] = 0.f;
            g_alpha[1][b * SS + s] = 0.f;
            g_alpha[2][b * SS + s] = 0.f;
            pq += mq; pa += ma; pn += mn;
        }
        for (int h = tid; h < HH; h += 256) {
            #pragma unroll
            for (int m = 0; m < 3; m++) {
                g_self[m][b * HH + h] = 0.f;
                g_cross[m][b * HH + h] = 0.f;
            }
        }
        #pragma unroll
        for (int o = 16; o > 0; o >>= 1) {
            pq += __shfl_down_sync(0xffffffffu, pq, o);
            pa += __shfl_down_sync(0xffffffffu, pa, o);
            pn += __shfl_down_sync(0xffffffffu, pn, o);
        }
        if (lane == 0) {
            redA[0 * 8 + wid] = pq; redA[1 * 8 + wid] = pa; redA[2 * 8 + wid] = pn;
        }
        __syncthreads();
        if (tid == 0) {
            float s0 = 0.f, s1 = 0.f, s2 = 0.f;
            for (int w = 0; w < 8; w++) { s0 += redA[w]; s1 += redA[8 + w]; s2 += redA[16 + w]; }
            g_msum[0][b] = s0; g_msum[1][b] = s1; g_msum[2][b] = s2;
        }
        SIGNAL(&mask_ready[b]);
    }

    // ===================== Phase B: gram tiles (dynamic queue) ============
    const int wm = wid & 1, wn = wid >> 1;
    for (;;) {
        __syncthreads();
        if (tid == 0) s_job = atomicAdd(next_tile, 1);
        __syncthreads();
        const int job = s_job;
        if (job >= NTILE_JOBS) break;
        const int b = job / 10;
        const int I = cTI[job % 10], J = cTJ[job % 10];
        const int s0 = I * TM, t0 = J * TN;
        const int* tb = turn + b * SS;
        if (tb[t0] - tb[s0 + TM - 1] > VR) {   // pruned (sorted turns, J>=I)
            __syncthreads();
            if (tid == 0) atomicAdd(&tiles_done[b], 1);
            continue;
        }
        const bool diag = (I == J);
        WAITC(&mask_ready[b], 1);

        int*   turnT = (int*)(smem + SM_TURNT);
        int*   turnS = (int*)(smem + SM_TURNS);
        float* wqT = (float*)(smem + SM_WQT);
        float* waT = (float*)(smem + SM_WAT);
        float* wnT = (float*)(smem + SM_WNT);
        float* mqS = (float*)(smem + SM_MQS);
        float* maS = (float*)(smem + SM_MAS);
        float* mnS = (float*)(smem + SM_MNS);
        float* sWq = (float*)(smem + SM_SWQ);
        float* sWa = (float*)(smem + SM_SWA);
        float* sWn = (float*)(smem + SM_SWN);
        if (tid < 128) {
            int gt = b * SS + t0 + tid;
            float mq = g_mask[0][gt], ma = g_mask[1][gt], mn = g_mask[2][gt];
            wqT[tid] = ma + mn; waT[tid] = mq + mn; wnT[tid] = mq + ma;
            turnT[tid] = tb[t0 + tid];
            int gs = b * SS + s0 + tid;
            float mqs = g_mask[0][gs], mas = g_mask[1][gs], mns = g_mask[2][gs];
            mqS[tid] = mqs; maS[tid] = mas; mnS[tid] = mns;
            sWq[tid] = mas + mns; sWa[tid] = mqs + mns; sWn[tid] = mqs + mas;
            turnS[tid] = tb[s0 + tid];
        }

        float acc[4][4][4];
        #pragma unroll
        for (int mi = 0; mi < 4; mi++)
            #pragma unroll
            for (int ni = 0; ni < 4; ni++)
                #pragma unroll
                for (int e = 0; e < 4; e++) acc[mi][ni][e] = 0.f;

        const int rA = wm * 64 + (lane & 15);
        const int kAe = (lane >> 4) * 16;
        const int rB = wn * 32 + ((lane >> 4) & 1) * 8 + (lane & 7);
        const int kBe = ((lane >> 3) & 1) * 16;
        const uint32_t bBase = diag ? (uint32_t)A_HI : (uint32_t)B_HI;

        uint32_t uOff[8];
        const float* uPtr[8];
        #pragma unroll
        for (int u = 0; u < 8; u++) {
            int unit = tid + u * 256;
            int isB = unit >> 10;
            int loc = unit & 1023;
            int row = loc >> 3, ucol = loc & 7;
            uOff[u] = swz128((uint32_t)(row * 128 + ucol * 16));
            uPtr[u] = x + ((size_t)b * SS + (isB ? t0 : s0) + row) * HH + ucol * 8;
        }

        {   // prologue
            char* stgp = smem + SM_STAGE;
            #pragma unroll
            for (int u = 0; u < 4; u++) {
                float4 v0 = *(const float4*)(uPtr[u]);
                float4 v1 = *(const float4*)(uPtr[u] + 4);
                cvt_store_hi(stgp, A_HI, uOff[u], v0, v1);
            }
            if (!diag) {
                #pragma unroll
                for (int u = 4; u < 8; u++) {
                    float4 v0 = *(const float4*)(uPtr[u]);
                    float4 v1 = *(const float4*)(uPtr[u] + 4);
                    cvt_store_hi(stgp, B_HI, uOff[u], v0, v1);
                }
            }
        }
        __syncthreads();

        for (int i = 0; i < NCHUNK; i++) {
            const uint32_t stg = sb + SM_STAGE + (uint32_t)(i & 1) * STAGE_BYTES;
            char* stgn = smem + SM_STAGE + ((i + 1) & 1) * STAGE_BYTES;
            const bool more = (i + 1 < NCHUNK);
            const int kn = (i + 1) * KC;

            float4 p0[4], p1[4];
            if (more) {
                #pragma unroll
                for (int u = 0; u < 4; u++) {
                    p0[u] = *(const float4*)(uPtr[u] + kn);
                    p1[u] = *(const float4*)(uPtr[u] + kn + 4);
                }
            }
            #pragma unroll
            for (int kk = 0; kk < 2; kk++) {
                const uint32_t kb = kk * 32;
                uint32_t bh[2][4];
                #pragma unroll
                for (int nb = 0; nb < 2; nb++) {
                    uint32_t roff = (uint32_t)((rB + nb * 16) * 128 + kb + kBe);
                    ldmx4(bh[nb], stg + bBase + swz128(roff));
                }
                uint32_t ah[4][4];
                #pragma unroll
                for (int mi = 0; mi < 4; mi++) {
                    uint32_t roff = (uint32_t)((rA + mi * 16) * 128 + kb + kAe);
                    ldmx4(ah[mi], stg + A_HI + swz128(roff));
                }
                #pragma unroll
                for (int mi = 0; mi < 4; mi++)
                    #pragma unroll
                    for (int ni = 0; ni < 4; ni++)
                        mma16816(acc[mi][ni], ah[mi], &bh[ni >> 1][2 * (ni & 1)]);
            }
            if (more) {
                #pragma unroll
                for (int u = 0; u < 4; u++)
                    cvt_store_hi(stgn, A_HI, uOff[u], p0[u], p1[u]);
                if (!diag) {
                    #pragma unroll
                    for (int u = 0; u < 4; u++) {
                        p0[u] = *(const float4*)(uPtr[u + 4] + kn);
                        p1[u] = *(const float4*)(uPtr[u + 4] + kn + 4);
                    }
                }
            }
            #pragma unroll
            for (int kk = 2; kk < 4; kk++) {
                const uint32_t kb = kk * 32;
                uint32_t bh[2][4];
                #pragma unroll
                for (int nb = 0; nb < 2; nb++) {
                    uint32_t roff = (uint32_t)((rB + nb * 16) * 128 + kb + kBe);
                    ldmx4(bh[nb], stg + bBase + swz128(roff));
                }
                uint32_t ah[4][4];
                #pragma unroll
                for (int mi = 0; mi < 4; mi++) {
                    uint32_t roff = (uint32_t)((rA + mi * 16) * 128 + kb + kAe);
                    ldmx4(ah[mi], stg + A_HI + swz128(roff));
                }
                #pragma unroll
                for (int mi = 0; mi < 4; mi++)
                    #pragma unroll
                    for (int ni = 0; ni < 4; ni++)
                        mma16816(acc[mi][ni], ah[mi], &bh[ni >> 1][2 * (ni & 1)]);
            }
            if (more && !diag) {
                #pragma unroll
                for (int u = 0; u < 4; u++)
                    cvt_store_hi(stgn, B_HI, uOff[u + 4], p0[u], p1[u]);
            }
            __syncthreads();
        }

        // epilogue: W into smem, dual gemv, atomic alpha
        float* Wb = (float*)(smem + SM_STAGE);
        #pragma unroll
        for (int mi = 0; mi < 4; mi++) {
            int r0 = wm * 64 + mi * 16 + (lane >> 2);
            int r1 = r0 + 8;
            float mq0 = mqS[r0], ma0 = maS[r0], mn0 = mnS[r0];
            float mq1 = mqS[r1], ma1 = maS[r1], mn1 = mnS[r1];
            int tn0 = turnS[r0], tn1 = turnS[r1];
            #pragma unroll
            for (int ni = 0; ni < 4; ni++) {
                int tb0 = wn * 32 + ni * 8 + (lane & 3) * 2;
                #pragma unroll
                for (int e = 0; e < 4; e++) {
                    int srow = (e >> 1) ? r1 : r0;
                    int tcol = tb0 + (e & 1);
                    float mq_ = (e >> 1) ? mq1 : mq0;
                    float ma_ = (e >> 1) ? ma1 : ma0;
                    float mn_ = (e >> 1) ? mn1 : mn0;
                    int tn_ = (e >> 1) ? tn1 : tn0;
                    int dt = turnT[tcol] - tn_;
                    float coef = fmaf(mq_, wqT[tcol], fmaf(ma_, waT[tcol], mn_ * wnT[tcol]));
                    float v = (dt >= -VR && dt <= VR) ? coef * acc[mi][ni][e] : 0.f;
                    Wb[srow * WSTRIDE + tcol] = v;
                }
            }
        }
        __syncthreads();
        if (tid < 128) {
            float aq = 0.f, aa = 0.f, an = 0.f;
            #pragma unroll 4
            for (int s = 0; s < 128; s++) {
                float wv = Wb[s * WSTRIDE + tid];
                aq = fmaf(sWq[s], wv, aq);
                aa = fmaf(sWa[s], wv, aa);
                an = fmaf(sWn[s], wv, an);
            }
            atomicAdd(&g_alpha[0][b * SS + t0 + tid], aq);
            atomicAdd(&g_alpha[1][b * SS + t0 + tid], aa);
            atomicAdd(&g_alpha[2][b * SS + t0 + tid], an);
            if (!diag) {
                float bq = 0.f, ba = 0.f, bn = 0.f;
                #pragma unroll 4
                for (int t = 0; t < 128; t++) {
                    float wv = Wb[tid * WSTRIDE + t];
                    bq = fmaf(wqT[t], wv, bq);
                    ba = fmaf(waT[t], wv, ba);
                    bn = fmaf(wnT[t], wv, bn);
                }
                atomicAdd(&g_alpha[0][b * SS + s0 + tid], bq);
                atomicAdd(&g_alpha[1][b * SS + s0 + tid], ba);
                atomicAdd(&g_alpha[2][b * SS + s0 + tid], bn);
            }
        }
        SIGNAL(&tiles_done[b]);
    }

    // ===================== Phase C: streaming chunks (dynamic queue) ======
    for (;;) {
        __syncthreads();
        if (tid == 0) s_job = atomicAdd(next_chunk, 1);
        __syncthreads();
        const int job = s_job;
        if (job >= NCHUNK_JOBS) break;
        const int b = job / SPLITS;
        const int sc = job % SPLITS;
        const int sbase = sc * SCHUNK;
        WAITC(&tiles_done[b], 10);

        float* smq = (float*)(smem + 0);
        float* sma = (float*)(smem + 256);
        float* smn = (float*)(smem + 512);
        float* scq = (float*)(smem + 768);
        float* sca = (float*)(smem + 1024);
        float* scn = (float*)(smem + 1280);
        if (tid < SCHUNK) {
            int gs = b * SS + sbase + tid;
            float mq = g_mask[0][gs], ma = g_mask[1][gs], mn = g_mask[2][gs];
            smq[tid] = mq; sma[tid] = ma; smn[tid] = mn;
            scq[tid] = mq * g_alpha[0][gs];
            sca[tid] = ma * g_alpha[1][gs];
            scn[tid] = mn * g_alpha[2][gs];
        }
        __syncthreads();

        if (tid < 192) {
            float m0 = g_msum[0][b], m1 = g_msum[1][b], m2 = g_msum[2][b];
            float rsq = 1.f / (m0 + AVG_EPS_);
            float rsa = 1.f / (m1 + AVG_EPS_);
            float rsn = 1.f / (m2 + AVG_EPS_);
            float rcq = 1.f / (m1 + m2 + AVG_EPS_);
            float rca = 1.f / (m0 + m2 + AVG_EPS_);
            float rcn = 1.f / (m0 + m1 + AVG_EPS_);

            const float4* xb = (const float4*)(x + ((size_t)b * SS + sbase) * HH) + tid;
            float4 aq = {0,0,0,0}, aa = {0,0,0,0}, an = {0,0,0,0};
            float4 bq = {0,0,0,0}, ba = {0,0,0,0}, bn = {0,0,0,0};
            #pragma unroll 4
            for (int s = 0; s < SCHUNK; s++) {
                float4 v = xb[(size_t)s * (HH / 4)];
                float c;
                c = smq[s]; aq.x = fmaf(c, v.x, aq.x); aq.y = fmaf(c, v.y, aq.y); aq.z = fmaf(c, v.z, aq.z); aq.w = fmaf(c, v.w, aq.w);
                c = sma[s]; aa.x = fmaf(c, v.x, aa.x); aa.y = fmaf(c, v.y, aa.y); aa.z = fmaf(c, v.z, aa.z); aa.w = fmaf(c, v.w, aa.w);
                c = smn[s]; an.x = fmaf(c, v.x, an.x); an.y = fmaf(c, v.y, an.y); an.z = fmaf(c, v.z, an.z); an.w = fmaf(c, v.w, an.w);
                c = scq[s]; bq.x = fmaf(c, v.x, bq.x); bq.y = fmaf(c, v.y, bq.y); bq.z = fmaf(c, v.z, bq.z); bq.w = fmaf(c, v.w, bq.w);
                c = sca[s]; ba.x = fmaf(c, v.x, ba.x); ba.y = fmaf(c, v.y, ba.y); ba.z = fmaf(c, v.z, ba.z); ba.w = fmaf(c, v.w, ba.w);
                c = scn[s]; bn.x = fmaf(c, v.x, bn.x); bn.y = fmaf(c, v.y, bn.y); bn.z = fmaf(c, v.z, bn.z); bn.w = fmaf(c, v.w, bn.w);
            }
            const int h0 = b * HH + 4 * tid;
            atomicAdd(&g_self[0][h0 + 0], aq.x * rsq); atomicAdd(&g_self[0][h0 + 1], aq.y * rsq);
            atomicAdd(&g_self[0][h0 + 2], aq.z * rsq); atomicAdd(&g_self[0][h0 + 3], aq.w * rsq);
            atomicAdd(&g_self[1][h0 + 0], aa.x * rsa); atomicAdd(&g_self[1][h0 + 1], aa.y * rsa);
            atomicAdd(&g_self[1][h0 + 2], aa.z * rsa); atomicAdd(&g_self[1][h0 + 3], aa.w * rsa);
            atomicAdd(&g_self[2][h0 + 0], an.x * rsn); atomicAdd(&g_self[2][h0 + 1], an.y * rsn);
            atomicAdd(&g_self[2][h0 + 2], an.z * rsn); atomicAdd(&g_self[2][h0 + 3], an.w * rsn);
            atomicAdd(&g_cross[0][h0 + 0], bq.x * rcq); atomicAdd(&g_cross[0][h0 + 1], bq.y * rcq);
            atomicAdd(&g_cross[0][h0 + 2], bq.z * rcq); atomicAdd(&g_cross[0][h0 + 3], bq.w * rcq);
            atomicAdd(&g_cross[1][h0 + 0], ba.x * rca); atomicAdd(&g_cross[1][h0 + 1], ba.y * rca);
            atomicAdd(&g_cross[1][h0 + 2], ba.z * rca); atomicAdd(&g_cross[1][h0 + 3], ba.w * rca);
            atomicAdd(&g_cross[2][h0 + 0], bn.x * rcn); atomicAdd(&g_cross[2][h0 + 1], bn.y * rcn);
            atomicAdd(&g_cross[2][h0 + 2], bn.z * rcn); atomicAdd(&g_cross[2][h0 + 3], bn.w * rcn);
        }
        SIGNAL(&chunks_done[b]);
    }

    // ===================== Phase D: logits (blocks 0..71) =================
    if (bid < NB) {
        const int b = bid;
        WAITC(&chunks_done[b], SPLITS);
        float* red = (float*)smem;  // 9*8 floats
        float p[9];
        #pragma unroll
        for (int k = 0; k < 9; k++) p[k] = 0.f;
        for (int h = tid; h < HH; h += 256) {
            #pragma unroll
            for (int m = 0; m < 3; m++) {
                float sv = g_self[m][b * HH + h];
                float cv = g_cross[m][b * HH + h];
                p[m * 3 + 0] = fmaf(sv, cv, p[m * 3 + 0]);
                p[m * 3 + 1] = fmaf(sv, sv, p[m * 3 + 1]);
                p[m * 3 + 2] = fmaf(cv, cv, p[m * 3 + 2]);
            }
        }
        #pragma unroll
        for (int k = 0; k < 9; k++)
            #pragma unroll
            for (int o = 16; o > 0; o >>= 1)
                p[k] += __shfl_down_sync(0xffffffffu, p[k], o);
        if (lane == 0) {
            #pragma unroll
            for (int k = 0; k < 9; k++) red[k * 8 + wid] = p[k];
        }
        __syncthreads();
        if (tid == 0) {
            #pragma unroll
            for (int m = 0; m < 3; m++) {
                float dot = 0.f, n1 = 0.f, n2 = 0.f;
                for (int w = 0; w < 8; w++) {
                    dot += red[(m * 3 + 0) * 8 + w];
                    n1  += red[(m * 3 + 1) * 8 + w];
                    n2  += red[(m * 3 + 2) * 8 + w];
                }
                float nx = fmaxf(sqrtf(n1), COS_EPS_);
                float ny = fmaxf(sqrtf(n2), COS_EPS_);
                float c = dot / (nx * ny);
                g_logits[m][b] = (c == 1.0f) ? __int_as_float(0x7fc00000) : c / TEMP_;
            }
        }
        if (b % SN == 0) {
            int g = b / SN;
            for (int h = tid; h < HH; h += 256) {
                out[1 + 0 * NG * HH + g * HH + h] = g_self[0][b * HH + h];
                out[1 + 1 * NG * HH + g * HH + h] = g_self[1][b * HH + h];
                out[1 + 2 * NG * HH + g * HH + h] = g_self[2][b * HH + h];
            }
        }
        SIGNAL(logits_done);
    }

    // ===================== Phase E: loss (block 0, thread 0) ==============
    if (bid == 0 && tid == 0) {
        while (atomicAdd(logits_done, 0) < NB) __nanosleep(128);
        __threadfence();
        float losses[3];
        for (int m = 0; m < 3; m++) {
            float sum = 0.f;
            int cnt = 0;
            for (int g = 0; g < NG; g++) {
                float l[SN];
                bool bad = false;
                for (int j = 0; j < SN; j++) {
                    l[j] = g_logits[m][g * SN + j];
                    if (isnan(l[j])) bad = true;
                }
                if (bad) continue;
                float mx = l[0];
                for (int j = 1; j < SN; j++) mx = fmaxf(mx, l[j]);
                float se = 0.f;
                for (int j = 0; j < SN; j++) se += expf(l[j] - mx);
                float lse = mx + logf(se);
                for (int j = 0; j < SN; j++) sum += (l[j] - lse) * labels[g * SN + j];
                cnt += SN;
            }
            losses[m] = -(sum / (float)cnt);
        }
        out[0] = (losses[1] + losses[0] + losses[2]) / 3.0f;
    }
}

// ---------------------------------------------------------------------------
extern "C" void kernel_launch(void* const* d_in, const int* in_sizes, int n_in,
                              void* d_out, int out_size) {
    const float* x      = (const float*)d_in[0];
    const float* am     = (const float*)d_in[1];
    const float* labels = (const float*)d_in[2];
    const int*   qa     = (const int*)d_in[3];
    const int*   turn   = (const int*)d_in[4];
    float* out = (float*)d_out;

    cudaFuncSetAttribute(k_persist, cudaFuncAttributeMaxDynamicSharedMemorySize, SMEM_BYTES);

    k_reset<<<1, 256>>>();
    k_persist<<<GRID, 256, SMEM_BYTES>>>(x, am, qa, turn, labels, out);
}

// round 16
// speedup vs baseline: 1.0048x; 1.0048x over previous
#include <cuda_runtime.h>
#include <cuda_fp16.h>
#include <math.h>
#include <cstdint>

namespace {
constexpr int NB = 72;
constexpr int SS = 512;
constexpr int HH = 768;
constexpr int NG = 8;
constexpr int SN = 9;
constexpr float TEMP_ = 0.07f;
constexpr float AVG_EPS_ = 1e-6f;
constexpr float COS_EPS_ = 1e-8f;
constexpr int VR = 2;
constexpr int SPLITS = 8;
constexpr int SCHUNK = SS / SPLITS;  // 64

constexpr int TM = 128, TN = 128, KC = 64;
constexpr int NCHUNK = HH / KC;  // 12

// smem layout (dynamic, 72192 B)
constexpr int SM_TURNT = 0;
constexpr int SM_TURNS = 512;
constexpr int SM_WQT   = 1024;
constexpr int SM_WAT   = 1536;
constexpr int SM_WNT   = 2048;
constexpr int SM_MQS   = 2560;
constexpr int SM_MAS   = 3072;
constexpr int SM_MNS   = 3584;
constexpr int SM_SWQ   = 4096;
constexpr int SM_SWA   = 4608;
constexpr int SM_SWN   = 5120;
constexpr int SM_STAGE = 6144;
constexpr int STAGE_BYTES = 32768;
constexpr int A_HI = 0, B_HI = 16384;
constexpr int WSTRIDE = 129;
constexpr int SMEM_BYTES = SM_STAGE + 128 * WSTRIDE * 4;  // 72192

constexpr int GRID = 296;          // 2 CTAs/SM * 148 SMs; all co-resident
constexpr int NTILE_JOBS = NB * 10;   // 720
constexpr int NCHUNK_JOBS = NB * SPLITS;  // 576
}

// Scratch
__device__ float g_mask[3][NB * SS];
__device__ float g_msum[3][NB];
__device__ float g_self[3][NB * HH];
__device__ float g_alpha[3][NB * SS];
__device__ float g_cross[3][NB * HH];
__device__ float g_logits[3][NB];

// Sync state: [0,72) mask_ready, [72,144) tiles_done, [144,216) chunks_done,
//             [216] logits_done, [217] next_tile, [218] next_chunk
__device__ int g_sync[219];

__device__ __constant__ int cTI[10] = {0,0,0,0,1,1,1,2,2,3};
__device__ __constant__ int cTJ[10] = {0,1,2,3,1,2,3,2,3,3};

// ===================== helpers =====================
__device__ __forceinline__ uint32_t smem_u32(const void* p) {
    uint32_t a;
    asm("{ .reg .u64 t; cvta.to.shared.u64 t, %1; cvt.u32.u64 %0, t; }" : "=r"(a) : "l"(p));
    return a;
}
__device__ __forceinline__ uint32_t swz128(uint32_t off) { return off ^ ((off >> 3) & 0x70); }

__device__ __forceinline__ void ldmx4(uint32_t* r, uint32_t addr) {
    asm volatile("ldmatrix.sync.aligned.m8n8.x4.shared.b16 {%0,%1,%2,%3}, [%4];"
                 : "=r"(r[0]), "=r"(r[1]), "=r"(r[2]), "=r"(r[3]) : "r"(addr));
}
__device__ __forceinline__ void mma16816(float* d, const uint32_t* a, const uint32_t* b) {
    asm volatile(
        "mma.sync.aligned.m16n8k16.row.col.f32.f16.f16.f32 "
        "{%0,%1,%2,%3}, {%4,%5,%6,%7}, {%8,%9}, {%0,%1,%2,%3};"
        : "+f"(d[0]), "+f"(d[1]), "+f"(d[2]), "+f"(d[3])
        : "r"(a[0]), "r"(a[1]), "r"(a[2]), "r"(a[3]), "r"(b[0]), "r"(b[1]));
}
__device__ __forceinline__ uint32_t h2u(__half2 h) {
    return *reinterpret_cast<uint32_t*>(&h);
}
__device__ __forceinline__ void cvt_store_hi(char* stgp, int base, uint32_t off,
                                             const float4& v0, const float4& v1) {
    uint4 Hi;
    Hi.x = h2u(__floats2half2_rn(v0.x, v0.y));
    Hi.y = h2u(__floats2half2_rn(v0.z, v0.w));
    Hi.z = h2u(__floats2half2_rn(v1.x, v1.y));
    Hi.w = h2u(__floats2half2_rn(v1.z, v1.w));
    *(uint4*)(stgp + base + off) = Hi;
}

// signal: every thread fences its writes, barrier, tid0 bumps counter
#define SIGNAL(ctr) do { __threadfence(); __syncthreads(); \
    if (tid == 0) atomicAdd((ctr), 1); } while (0)
// wait: tid0 spins (acquire via atomic), barrier releases the block
#define WAITC(ctr, tgt) do { if (tid == 0) { \
    while (atomicAdd((ctr), 0) < (tgt)) __nanosleep(128); __threadfence(); } \
    __syncthreads(); } while (0)

// ---------------------------------------------------------------------------
__global__ void k_reset() {
    int i = threadIdx.x;
    if (i < 219) g_sync[i] = 0;
}

// ---------------------------------------------------------------------------
__global__ void __launch_bounds__(256, 2)
k_persist(const float* __restrict__ x,
          const float* __restrict__ am,
          const int* __restrict__ qa,
          const int* __restrict__ turn,
          const float* __restrict__ labels,
          float* __restrict__ out) {
    extern __shared__ char smem[];
    const uint32_t sb = smem_u32(smem);
    const int tid = threadIdx.x, bid = blockIdx.x;
    const int wid = tid >> 5, lane = tid & 31;
    int* mask_ready  = g_sync;
    int* tiles_done  = g_sync + 72;
    int* chunks_done = g_sync + 144;
    int* logits_done = g_sync + 216;
    int* next_tile   = g_sync + 217;
    int* next_chunk  = g_sync + 218;
    __shared__ int s_job;

    // ===================== Phase A: masks + msum + zero (blocks 0..71) ====
    if (bid < NB) {
        const int b = bid;
        float* redA = (float*)smem;  // 3*8 floats
        float pq = 0.f, pa = 0.f, pn = 0.f;
        for (int s = tid; s < SS; s += 256) {
            int q = qa[b * SS + s];
            float a = am[b * SS + s];
            float mq = (q == 1 || q == 2) ? a : 0.f;
            float ma = (q == 0 || q == 2) ? a : 0.f;
            float mn = (q == 3) ? a : 0.f;
            g_mask[0][b * SS + s] = mq;
            g_mask[1][b * SS + s] = ma;
            g_mask[2][b * SS + s] = mn;
            g_alpha[0][b * SS + s] = 0.f;
            g_alpha[1][b * SS + s] = 0.f;
            g_alpha[2][b * SS + s] = 0.f;
            pq += mq; pa += ma; pn += mn;
        }
        for (int h = tid; h < HH; h += 256) {
            #pragma unroll
            for (int m = 0; m < 3; m++) {
                g_self[m][b * HH + h] = 0.f;
                g_cross[m][b * HH + h] = 0.f;
            }
        }
        #pragma unroll
        for (int o = 16; o > 0; o >>= 1) {
            pq += __shfl_down_sync(0xffffffffu, pq, o);
            pa += __shfl_down_sync(0xffffffffu, pa, o);
            pn += __shfl_down_sync(0xffffffffu, pn, o);
        }
        if (lane == 0) {
            redA[0 * 8 + wid] = pq; redA[1 * 8 + wid] = pa; redA[2 * 8 + wid] = pn;
        }
        __syncthreads();
        if (tid == 0) {
            float s0 = 0.f, s1 = 0.f, s2 = 0.f;
            for (int w = 0; w < 8; w++) { s0 += redA[w]; s1 += redA[8 + w]; s2 += redA[16 + w]; }
            g_msum[0][b] = s0; g_msum[1][b] = s1; g_msum[2][b] = s2;
        }
        SIGNAL(&mask_ready[b]);
    }

    // ===================== Phase B: gram tiles (dynamic queue) ============
    const int wm = wid & 1, wn = wid >> 1;
    for (;;) {
        __syncthreads();
        if (tid == 0) s_job = atomicAdd(next_tile, 1);
        __syncthreads();
        const int job = s_job;
        if (job >= NTILE_JOBS) break;
        const int b = job / 10;
        const int I = cTI[job % 10], J = cTJ[job % 10];
        const int s0 = I * TM, t0 = J * TN;
        const int* tb = turn + b * SS;
        if (tb[t0] - tb[s0 + TM - 1] > VR) {   // pruned (sorted turns, J>=I)
            __syncthreads();
            if (tid == 0) atomicAdd(&tiles_done[b], 1);
            continue;
        }
        const bool diag = (I == J);
        WAITC(&mask_ready[b], 1);

        int*   turnT = (int*)(smem + SM_TURNT);
        int*   turnS = (int*)(smem + SM_TURNS);
        float* wqT = (float*)(smem + SM_WQT);
        float* waT = (float*)(smem + SM_WAT);
        float* wnT = (float*)(smem + SM_WNT);
        float* mqS = (float*)(smem + SM_MQS);
        float* maS = (float*)(smem + SM_MAS);
        float* mnS = (float*)(smem + SM_MNS);
        float* sWq = (float*)(smem + SM_SWQ);
        float* sWa = (float*)(smem + SM_SWA);
        float* sWn = (float*)(smem + SM_SWN);
        if (tid < 128) {
            int gt = b * SS + t0 + tid;
            float mq = g_mask[0][gt], ma = g_mask[1][gt], mn = g_mask[2][gt];
            wqT[tid] = ma + mn; waT[tid] = mq + mn; wnT[tid] = mq + ma;
            turnT[tid] = tb[t0 + tid];
            int gs = b * SS + s0 + tid;
            float mqs = g_mask[0][gs], mas = g_mask[1][gs], mns = g_mask[2][gs];
            mqS[tid] = mqs; maS[tid] = mas; mnS[tid] = mns;
            sWq[tid] = mas + mns; sWa[tid] = mqs + mns; sWn[tid] = mqs + mas;
            turnS[tid] = tb[s0 + tid];
        }

        float acc[4][4][4];
        #pragma unroll
        for (int mi = 0; mi < 4; mi++)
            #pragma unroll
            for (int ni = 0; ni < 4; ni++)
                #pragma unroll
                for (int e = 0; e < 4; e++) acc[mi][ni][e] = 0.f;

        const int rA = wm * 64 + (lane & 15);
        const int kAe = (lane >> 4) * 16;
        const int rB = wn * 32 + ((lane >> 4) & 1) * 8 + (lane & 7);
        const int kBe = ((lane >> 3) & 1) * 16;
        const uint32_t bBase = diag ? (uint32_t)A_HI : (uint32_t)B_HI;

        uint32_t uOff[8];
        const float* uPtr[8];
        #pragma unroll
        for (int u = 0; u < 8; u++) {
            int unit = tid + u * 256;
            int isB = unit >> 10;
            int loc = unit & 1023;
            int row = loc >> 3, ucol = loc & 7;
            uOff[u] = swz128((uint32_t)(row * 128 + ucol * 16));
            uPtr[u] = x + ((size_t)b * SS + (isB ? t0 : s0) + row) * HH + ucol * 8;
        }

        {   // prologue
            char* stgp = smem + SM_STAGE;
            #pragma unroll
            for (int u = 0; u < 4; u++) {
                float4 v0 = *(const float4*)(uPtr[u]);
                float4 v1 = *(const float4*)(uPtr[u] + 4);
                cvt_store_hi(stgp, A_HI, uOff[u], v0, v1);
            }
            if (!diag) {
                #pragma unroll
                for (int u = 4; u < 8; u++) {
                    float4 v0 = *(const float4*)(uPtr[u]);
                    float4 v1 = *(const float4*)(uPtr[u] + 4);
                    cvt_store_hi(stgp, B_HI, uOff[u], v0, v1);
                }
            }
        }
        __syncthreads();

        for (int i = 0; i < NCHUNK; i++) {
            const uint32_t stg = sb + SM_STAGE + (uint32_t)(i & 1) * STAGE_BYTES;
            char* stgn = smem + SM_STAGE + ((i + 1) & 1) * STAGE_BYTES;
            const bool more = (i + 1 < NCHUNK);
            const int kn = (i + 1) * KC;

            float4 p0[4], p1[4];
            if (more) {
                #pragma unroll
                for (int u = 0; u < 4; u++) {
                    p0[u] = *(const float4*)(uPtr[u] + kn);
                    p1[u] = *(const float4*)(uPtr[u] + kn + 4);
                }
            }
            #pragma unroll
            for (int kk = 0; kk < 2; kk++) {
                const uint32_t kb = kk * 32;
                uint32_t bh[2][4];
                #pragma unroll
                for (int nb = 0; nb < 2; nb++) {
                    uint32_t roff = (uint32_t)((rB + nb * 16) * 128 + kb + kBe);
                    ldmx4(bh[nb], stg + bBase + swz128(roff));
                }
                uint32_t ah[4][4];
                #pragma unroll
                for (int mi = 0; mi < 4; mi++) {
                    uint32_t roff = (uint32_t)((rA + mi * 16) * 128 + kb + kAe);
                    ldmx4(ah[mi], stg + A_HI + swz128(roff));
                }
                #pragma unroll
                for (int mi = 0; mi < 4; mi++)
                    #pragma unroll
                    for (int ni = 0; ni < 4; ni++)
                        mma16816(acc[mi][ni], ah[mi], &bh[ni >> 1][2 * (ni & 1)]);
            }
            if (more) {
                #pragma unroll
                for (int u = 0; u < 4; u++)
                    cvt_store_hi(stgn, A_HI, uOff[u], p0[u], p1[u]);
                if (!diag) {
                    #pragma unroll
                    for (int u = 0; u < 4; u++) {
                        p0[u] = *(const float4*)(uPtr[u + 4] + kn);
                        p1[u] = *(const float4*)(uPtr[u + 4] + kn + 4);
                    }
                }
            }
            #pragma unroll
            for (int kk = 2; kk < 4; kk++) {
                const uint32_t kb = kk * 32;
                uint32_t bh[2][4];
                #pragma unroll
                for (int nb = 0; nb < 2; nb++) {
                    uint32_t roff = (uint32_t)((rB + nb * 16) * 128 + kb + kBe);
                    ldmx4(bh[nb], stg + bBase + swz128(roff));
                }
                uint32_t ah[4][4];
                #pragma unroll
                for (int mi = 0; mi < 4; mi++) {
                    uint32_t roff = (uint32_t)((rA + mi * 16) * 128 + kb + kAe);
                    ldmx4(ah[mi], stg + A_HI + swz128(roff));
                }
                #pragma unroll
                for (int mi = 0; mi < 4; mi++)
                    #pragma unroll
                    for (int ni = 0; ni < 4; ni++)
                        mma16816(acc[mi][ni], ah[mi], &bh[ni >> 1][2 * (ni & 1)]);
            }
            if (more && !diag) {
                #pragma unroll
                for (int u = 0; u < 4; u++)
                    cvt_store_hi(stgn, B_HI, uOff[u + 4], p0[u], p1[u]);
            }
            __syncthreads();
        }

        // epilogue: W into smem, dual gemv, atomic alpha
        float* Wb = (float*)(smem + SM_STAGE);
        #pragma unroll
        for (int mi = 0; mi < 4; mi++) {
            int r0 = wm * 64 + mi * 16 + (lane >> 2);
            int r1 = r0 + 8;
            float mq0 = mqS[r0], ma0 = maS[r0], mn0 = mnS[r0];
            float mq1 = mqS[r1], ma1 = maS[r1], mn1 = mnS[r1];
            int tn0 = turnS[r0], tn1 = turnS[r1];
            #pragma unroll
            for (int ni = 0; ni < 4; ni++) {
                int tb0 = wn * 32 + ni * 8 + (lane & 3) * 2;
                #pragma unroll
                for (int e = 0; e < 4; e++) {
                    int srow = (e >> 1) ? r1 : r0;
                    int tcol = tb0 + (e & 1);
                    float mq_ = (e >> 1) ? mq1 : mq0;
                    float ma_ = (e >> 1) ? ma1 : ma0;
                    float mn_ = (e >> 1) ? mn1 : mn0;
                    int tn_ = (e >> 1) ? tn1 : tn0;
                    int dt = turnT[tcol] - tn_;
                    float coef = fmaf(mq_, wqT[tcol], fmaf(ma_, waT[tcol], mn_ * wnT[tcol]));
                    float v = (dt >= -VR && dt <= VR) ? coef * acc[mi][ni][e] : 0.f;
                    Wb[srow * WSTRIDE + tcol] = v;
                }
            }
        }
        __syncthreads();
        if (tid < 128) {
            float aq = 0.f, aa = 0.f, an = 0.f;
            #pragma unroll 4
            for (int s = 0; s < 128; s++) {
                float wv = Wb[s * WSTRIDE + tid];
                aq = fmaf(sWq[s], wv, aq);
                aa = fmaf(sWa[s], wv, aa);
                an = fmaf(sWn[s], wv, an);
            }
            atomicAdd(&g_alpha[0][b * SS + t0 + tid], aq);
            atomicAdd(&g_alpha[1][b * SS + t0 + tid], aa);
            atomicAdd(&g_alpha[2][b * SS + t0 + tid], an);
            if (!diag) {
                float bq = 0.f, ba = 0.f, bn = 0.f;
                #pragma unroll 4
                for (int t = 0; t < 128; t++) {
                    float wv = Wb[tid * WSTRIDE + t];
                    bq = fmaf(wqT[t], wv, bq);
                    ba = fmaf(waT[t], wv, ba);
                    bn = fmaf(wnT[t], wv, bn);
                }
                atomicAdd(&g_alpha[0][b * SS + s0 + tid], bq);
                atomicAdd(&g_alpha[1][b * SS + s0 + tid], ba);
                atomicAdd(&g_alpha[2][b * SS + s0 + tid], bn);
            }
        }
        SIGNAL(&tiles_done[b]);
    }

    // ===================== Phase C: streaming chunks (dynamic queue) ======
    for (;;) {
        __syncthreads();
        if (tid == 0) s_job = atomicAdd(next_chunk, 1);
        __syncthreads();
        const int job = s_job;
        if (job >= NCHUNK_JOBS) break;
        const int b = job / SPLITS;
        const int sc = job % SPLITS;
        const int sbase = sc * SCHUNK;
        WAITC(&tiles_done[b], 10);

        float* smq = (float*)(smem + 0);
        float* sma = (float*)(smem + 256);
        float* smn = (float*)(smem + 512);
        float* scq = (float*)(smem + 768);
        float* sca = (float*)(smem + 1024);
        float* scn = (float*)(smem + 1280);
        if (tid < SCHUNK) {
            int gs = b * SS + sbase + tid;
            float mq = g_mask[0][gs], ma = g_mask[1][gs], mn = g_mask[2][gs];
            smq[tid] = mq; sma[tid] = ma; smn[tid] = mn;
            scq[tid] = mq * g_alpha[0][gs];
            sca[tid] = ma * g_alpha[1][gs];
            scn[tid] = mn * g_alpha[2][gs];
        }
        __syncthreads();

        if (tid < 192) {
            float m0 = g_msum[0][b], m1 = g_msum[1][b], m2 = g_msum[2][b];
            float rsq = 1.f / (m0 + AVG_EPS_);
            float rsa = 1.f / (m1 + AVG_EPS_);
            float rsn = 1.f / (m2 + AVG_EPS_);
            float rcq = 1.f / (m1 + m2 + AVG_EPS_);
            float rca = 1.f / (m0 + m2 + AVG_EPS_);
            float rcn = 1.f / (m0 + m1 + AVG_EPS_);

            const float4* xb = (const float4*)(x + ((size_t)b * SS + sbase) * HH) + tid;
            float4 aq = {0,0,0,0}, aa = {0,0,0,0}, an = {0,0,0,0};
            float4 bq = {0,0,0,0}, ba = {0,0,0,0}, bn = {0,0,0,0};
            #pragma unroll 4
            for (int s = 0; s < SCHUNK; s++) {
                float4 v = xb[(size_t)s * (HH / 4)];
                float c;
                c = smq[s]; aq.x = fmaf(c, v.x, aq.x); aq.y = fmaf(c, v.y, aq.y); aq.z = fmaf(c, v.z, aq.z); aq.w = fmaf(c, v.w, aq.w);
                c = sma[s]; aa.x = fmaf(c, v.x, aa.x); aa.y = fmaf(c, v.y, aa.y); aa.z = fmaf(c, v.z, aa.z); aa.w = fmaf(c, v.w, aa.w);
                c = smn[s]; an.x = fmaf(c, v.x, an.x); an.y = fmaf(c, v.y, an.y); an.z = fmaf(c, v.z, an.z); an.w = fmaf(c, v.w, an.w);
                c = scq[s]; bq.x = fmaf(c, v.x, bq.x); bq.y = fmaf(c, v.y, bq.y); bq.z = fmaf(c, v.z, bq.z); bq.w = fmaf(c, v.w, bq.w);
                c = sca[s]; ba.x = fmaf(c, v.x, ba.x); ba.y = fmaf(c, v.y, ba.y); ba.z = fmaf(c, v.z, ba.z); ba.w = fmaf(c, v.w, ba.w);
                c = scn[s]; bn.x = fmaf(c, v.x, bn.x); bn.y = fmaf(c, v.y, bn.y); bn.z = fmaf(c, v.z, bn.z); bn.w = fmaf(c, v.w, bn.w);
            }
            const int h0 = b * HH + 4 * tid;
            atomicAdd(&g_self[0][h0 + 0], aq.x * rsq); atomicAdd(&g_self[0][h0 + 1], aq.y * rsq);
            atomicAdd(&g_self[0][h0 + 2], aq.z * rsq); atomicAdd(&g_self[0][h0 + 3], aq.w * rsq);
            atomicAdd(&g_self[1][h0 + 0], aa.x * rsa); atomicAdd(&g_self[1][h0 + 1], aa.y * rsa);
            atomicAdd(&g_self[1][h0 + 2], aa.z * rsa); atomicAdd(&g_self[1][h0 + 3], aa.w * rsa);
            atomicAdd(&g_self[2][h0 + 0], an.x * rsn); atomicAdd(&g_self[2][h0 + 1], an.y * rsn);
            atomicAdd(&g_self[2][h0 + 2], an.z * rsn); atomicAdd(&g_self[2][h0 + 3], an.w * rsn);
            atomicAdd(&g_cross[0][h0 + 0], bq.x * rcq); atomicAdd(&g_cross[0][h0 + 1], bq.y * rcq);
            atomicAdd(&g_cross[0][h0 + 2], bq.z * rcq); atomicAdd(&g_cross[0][h0 + 3], bq.w * rcq);
            atomicAdd(&g_cross[1][h0 + 0], ba.x * rca); atomicAdd(&g_cross[1][h0 + 1], ba.y * rca);
            atomicAdd(&g_cross[1][h0 + 2], ba.z * rca); atomicAdd(&g_cross[1][h0 + 3], ba.w * rca);
            atomicAdd(&g_cross[2][h0 + 0], bn.x * rcn); atomicAdd(&g_cross[2][h0 + 1], bn.y * rcn);
            atomicAdd(&g_cross[2][h0 + 2], bn.z * rcn); atomicAdd(&g_cross[2][h0 + 3], bn.w * rcn);
        }
        SIGNAL(&chunks_done[b]);
    }

    // ===================== Phase D: logits (blocks 0..71) =================
    if (bid < NB) {
        const int b = bid;
        WAITC(&chunks_done[b], SPLITS);
        float* red = (float*)smem;  // 9*8 floats
        float p[9];
        #pragma unroll
        for (int k = 0; k < 9; k++) p[k] = 0.f;
        for (int h = tid; h < HH; h += 256) {
            #pragma unroll
            for (int m = 0; m < 3; m++) {
                float sv = g_self[m][b * HH + h];
                float cv = g_cross[m][b * HH + h];
                p[m * 3 + 0] = fmaf(sv, cv, p[m * 3 + 0]);
                p[m * 3 + 1] = fmaf(sv, sv, p[m * 3 + 1]);
                p[m * 3 + 2] = fmaf(cv, cv, p[m * 3 + 2]);
            }
        }
        #pragma unroll
        for (int k = 0; k < 9; k++)
            #pragma unroll
            for (int o = 16; o > 0; o >>= 1)
                p[k] += __shfl_down_sync(0xffffffffu, p[k], o);
        if (lane == 0) {
            #pragma unroll
            for (int k = 0; k < 9; k++) red[k * 8 + wid] = p[k];
        }
        __syncthreads();
        if (tid == 0) {
            #pragma unroll
            for (int m = 0; m < 3; m++) {
                float dot = 0.f, n1 = 0.f, n2 = 0.f;
                for (int w = 0; w < 8; w++) {
                    dot += red[(m * 3 + 0) * 8 + w];
                    n1  += red[(m * 3 + 1) * 8 + w];
                    n2  += red[(m * 3 + 2) * 8 + w];
                }
                float nx = fmaxf(sqrtf(n1), COS_EPS_);
                float ny = fmaxf(sqrtf(n2), COS_EPS_);
                float c = dot / (nx * ny);
                g_logits[m][b] = (c == 1.0f) ? __int_as_float(0x7fc00000) : c / TEMP_;
            }
        }
        if (b % SN == 0) {
            int g = b / SN;
            for (int h = tid; h < HH; h += 256) {
                out[1 + 0 * NG * HH + g * HH + h] = g_self[0][b * HH + h];
                out[1 + 1 * NG * HH + g * HH + h] = g_self[1][b * HH + h];
                out[1 + 2 * NG * HH + g * HH + h] = g_self[2][b * HH + h];
            }
        }
        SIGNAL(logits_done);
    }

    // ===================== Phase E: loss (block 0, thread 0) ==============
    if (bid == 0 && tid == 0) {
        while (atomicAdd(logits_done, 0) < NB) __nanosleep(128);
        __threadfence();
        float losses[3];
        for (int m = 0; m < 3; m++) {
            float sum = 0.f;
            int cnt = 0;
            for (int g = 0; g < NG; g++) {
                float l[SN];
                bool bad = false;
                for (int j = 0; j < SN; j++) {
                    l[j] = g_logits[m][g * SN + j];
                    if (isnan(l[j])) bad = true;
                }
                if (bad) continue;
                float mx = l[0];
                for (int j = 1; j < SN; j++) mx = fmaxf(mx, l[j]);
                float se = 0.f;
                for (int j = 0; j < SN; j++) se += expf(l[j] - mx);
                float lse = mx + logf(se);
                for (int j = 0; j < SN; j++) sum += (l[j] - lse) * labels[g * SN + j];
                cnt += SN;
            }
            losses[m] = -(sum / (float)cnt);
        }
        out[0] = (losses[1] + losses[0] + losses[2]) / 3.0f;
    }
}

// ---------------------------------------------------------------------------
extern "C" void kernel_launch(void* const* d_in, const int* in_sizes, int n_in,
                              void* d_out, int out_size) {
    const float* x      = (const float*)d_in[0];
    const float* am     = (const float*)d_in[1];
    const float* labels = (const float*)d_in[2];
    const int*   qa     = (const int*)d_in[3];
    const int*   turn   = (const int*)d_in[4];
    float* out = (float*)d_out;

    cudaFuncSetAttribute(k_persist, cudaFuncAttributeMaxDynamicSharedMemorySize, SMEM_BYTES);

    k_reset<<<1, 256>>>();
    k_persist<<<GRID, 256, SMEM_BYTES>>>(x, am, qa, turn, labels, out);
}

// round 17
// speedup vs baseline: 1.0238x; 1.0189x over previous
#include <cuda_runtime.h>
#include <cuda_fp16.h>
#include <math.h>
#include <cstdint>

namespace {
constexpr int NB = 72;
constexpr int SS = 512;
constexpr int HH = 768;
constexpr int NG = 8;
constexpr int SN = 9;
constexpr float TEMP_ = 0.07f;
constexpr float AVG_EPS_ = 1e-6f;
constexpr float COS_EPS_ = 1e-8f;
constexpr int VR = 2;
constexpr int SPLITS = 8;
constexpr int SCHUNK = SS / SPLITS;  // 64

constexpr int TM = 128, TN = 128, KC = 64;
constexpr int NCHUNK = HH / KC;  // 12

// smem layout (dynamic, 72192 B)
constexpr int SM_TURNT = 0;
constexpr int SM_TURNS = 512;
constexpr int SM_WQT   = 1024;
constexpr int SM_WAT   = 1536;
constexpr int SM_WNT   = 2048;
constexpr int SM_MQS   = 2560;
constexpr int SM_MAS   = 3072;
constexpr int SM_MNS   = 3584;
constexpr int SM_SWQ   = 4096;
constexpr int SM_SWA   = 4608;
constexpr int SM_SWN   = 5120;
constexpr int SM_STAGE = 6144;
constexpr int STAGE_BYTES = 32768;
constexpr int A_HI = 0, B_HI = 16384;
constexpr int WSTRIDE = 129;
constexpr int SMEM_BYTES = SM_STAGE + 128 * WSTRIDE * 4;  // 72192

constexpr int GRID = 296;          // 2 CTAs/SM * 148 SMs; all co-resident
constexpr int NTILE_JOBS = NB * 10;   // 720
constexpr int NCHUNK_JOBS = NB * SPLITS;  // 576
}

// Scratch
__device__ float g_mask[3][NB * SS];
__device__ float g_msum[3][NB];
__device__ float g_self[3][NB * HH];
__device__ float g_alpha[3][NB * SS];
__device__ float g_cross[3][NB * HH];
__device__ float g_logits[3][NB];

// Sync state: [0,72) mask_ready, [72,144) tiles_done, [144,216) chunks_done,
//             [216] logits_done, [217] next_tile, [218] next_chunk
__device__ int g_sync[219];

__device__ __constant__ int cTI[10] = {0,0,0,0,1,1,1,2,2,3};
__device__ __constant__ int cTJ[10] = {0,1,2,3,1,2,3,2,3,3};

// ===================== helpers =====================
__device__ __forceinline__ uint32_t smem_u32(const void* p) {
    uint32_t a;
    asm("{ .reg .u64 t; cvta.to.shared.u64 t, %1; cvt.u32.u64 %0, t; }" : "=r"(a) : "l"(p));
    return a;
}
__device__ __forceinline__ uint32_t swz128(uint32_t off) { return off ^ ((off >> 3) & 0x70); }

__device__ __forceinline__ void ldmx4(uint32_t* r, uint32_t addr) {
    asm volatile("ldmatrix.sync.aligned.m8n8.x4.shared.b16 {%0,%1,%2,%3}, [%4];"
                 : "=r"(r[0]), "=r"(r[1]), "=r"(r[2]), "=r"(r[3]) : "r"(addr));
}
__device__ __forceinline__ void mma16816(float* d, const uint32_t* a, const uint32_t* b) {
    asm volatile(
        "mma.sync.aligned.m16n8k16.row.col.f32.f16.f16.f32 "
        "{%0,%1,%2,%3}, {%4,%5,%6,%7}, {%8,%9}, {%0,%1,%2,%3};"
        : "+f"(d[0]), "+f"(d[1]), "+f"(d[2]), "+f"(d[3])
        : "r"(a[0]), "r"(a[1]), "r"(a[2]), "r"(a[3]), "r"(b[0]), "r"(b[1]));
}
__device__ __forceinline__ uint32_t h2u(__half2 h) {
    return *reinterpret_cast<uint32_t*>(&h);
}
__device__ __forceinline__ void cvt_store_hi(char* stgp, int base, uint32_t off,
                                             const float4& v0, const float4& v1) {
    uint4 Hi;
    Hi.x = h2u(__floats2half2_rn(v0.x, v0.y));
    Hi.y = h2u(__floats2half2_rn(v0.z, v0.w));
    Hi.z = h2u(__floats2half2_rn(v1.x, v1.y));
    Hi.w = h2u(__floats2half2_rn(v1.z, v1.w));
    *(uint4*)(stgp + base + off) = Hi;
}

// signal: every thread fences its writes, barrier, tid0 bumps counter
#define SIGNAL(ctr) do { __threadfence(); __syncthreads(); \
    if (tid == 0) atomicAdd((ctr), 1); } while (0)
// wait: tid0 spins (acquire via atomic), barrier releases the block
#define WAITC(ctr, tgt) do { if (tid == 0) { \
    while (atomicAdd((ctr), 0) < (tgt)) __nanosleep(128); __threadfence(); } \
    __syncthreads(); } while (0)

// ---------------------------------------------------------------------------
__global__ void k_reset() {
    int i = threadIdx.x;
    if (i < 219) g_sync[i] = 0;
}

// ---------------------------------------------------------------------------
__global__ void __launch_bounds__(256, 2)
k_persist(const float* __restrict__ x,
          const float* __restrict__ am,
          const int* __restrict__ qa,
          const int* __restrict__ turn,
          const float* __restrict__ labels,
          float* __restrict__ out) {
    extern __shared__ char smem[];
    const uint32_t sb = smem_u32(smem);
    const int tid = threadIdx.x, bid = blockIdx.x;
    const int wid = tid >> 5, lane = tid & 31;
    int* mask_ready  = g_sync;
    int* tiles_done  = g_sync + 72;
    int* chunks_done = g_sync + 144;
    int* logits_done = g_sync + 216;
    int* next_tile   = g_sync + 217;
    int* next_chunk  = g_sync + 218;
    __shared__ int s_job;

    // ===================== Phase A: masks + msum + zero (blocks 0..71) ====
    if (bid < NB) {
        const int b = bid;
        float* redA = (float*)smem;  // 3*8 floats
        float pq = 0.f, pa = 0.f, pn = 0.f;
        for (int s = tid; s < SS; s += 256) {
            int q = qa[b * SS + s];
            float a = am[b * SS + s];
            float mq = (q == 1 || q == 2) ? a : 0.f;
            float ma = (q == 0 || q == 2) ? a : 0.f;
            float mn = (q == 3) ? a : 0.f;
            g_mask[0][b * SS + s] = mq;
            g_mask[1][b * SS + s] = ma;
            g_mask[2][b * SS + s] = mn;
            g_alpha[0][b * SS + s] = 0.f;
            g_alpha[1][b * SS + s] = 0.f;
            g_alpha[2][b * SS + s] = 0.f;
            pq += mq; pa += ma; pn += mn;
        }
        for (int h = tid; h < HH; h += 256) {
            #pragma unroll
            for (int m = 0; m < 3; m++) {
                g_self[m][b * HH + h] = 0.f;
                g_cross[m][b * HH + h] = 0.f;
            }
        }
        #pragma unroll
        for (int o = 16; o > 0; o >>= 1) {
            pq += __shfl_down_sync(0xffffffffu, pq, o);
            pa += __shfl_down_sync(0xffffffffu, pa, o);
            pn += __shfl_down_sync(0xffffffffu, pn, o);
        }
        if (lane == 0) {
            redA[0 * 8 + wid] = pq; redA[1 * 8 + wid] = pa; redA[2 * 8 + wid] = pn;
        }
        __syncthreads();
        if (tid == 0) {
            float s0 = 0.f, s1 = 0.f, s2 = 0.f;
            for (int w = 0; w < 8; w++) { s0 += redA[w]; s1 += redA[8 + w]; s2 += redA[16 + w]; }
            g_msum[0][b] = s0; g_msum[1][b] = s1; g_msum[2][b] = s2;
        }
        SIGNAL(&mask_ready[b]);
    }

    // ===================== Phase B: gram tiles (dynamic queue) ============
    const int wm = wid & 1, wn = wid >> 1;
    for (;;) {
        __syncthreads();
        if (tid == 0) s_job = atomicAdd(next_tile, 1);
        __syncthreads();
        const int job = s_job;
        if (job >= NTILE_JOBS) break;
        const int b = job / 10;
        const int I = cTI[job % 10], J = cTJ[job % 10];
        const int s0 = I * TM, t0 = J * TN;
        const int* tb = turn + b * SS;
        if (tb[t0] - tb[s0 + TM - 1] > VR) {   // pruned (sorted turns, J>=I)
            __syncthreads();
            if (tid == 0) atomicAdd(&tiles_done[b], 1);
            continue;
        }
        const bool diag = (I == J);
        WAITC(&mask_ready[b], 1);

        int*   turnT = (int*)(smem + SM_TURNT);
        int*   turnS = (int*)(smem + SM_TURNS);
        float* wqT = (float*)(smem + SM_WQT);
        float* waT = (float*)(smem + SM_WAT);
        float* wnT = (float*)(smem + SM_WNT);
        float* mqS = (float*)(smem + SM_MQS);
        float* maS = (float*)(smem + SM_MAS);
        float* mnS = (float*)(smem + SM_MNS);
        float* sWq = (float*)(smem + SM_SWQ);
        float* sWa = (float*)(smem + SM_SWA);
        float* sWn = (float*)(smem + SM_SWN);
        if (tid < 128) {
            int gt = b * SS + t0 + tid;
            float mq = g_mask[0][gt], ma = g_mask[1][gt], mn = g_mask[2][gt];
            wqT[tid] = ma + mn; waT[tid] = mq + mn; wnT[tid] = mq + ma;
            turnT[tid] = tb[t0 + tid];
            int gs = b * SS + s0 + tid;
            float mqs = g_mask[0][gs], mas = g_mask[1][gs], mns = g_mask[2][gs];
            mqS[tid] = mqs; maS[tid] = mas; mnS[tid] = mns;
            sWq[tid] = mas + mns; sWa[tid] = mqs + mns; sWn[tid] = mqs + mas;
            turnS[tid] = tb[s0 + tid];
        }

        float acc[4][4][4];
        #pragma unroll
        for (int mi = 0; mi < 4; mi++)
            #pragma unroll
            for (int ni = 0; ni < 4; ni++)
                #pragma unroll
                for (int e = 0; e < 4; e++) acc[mi][ni][e] = 0.f;

        const int rA = wm * 64 + (lane & 15);
        const int kAe = (lane >> 4) * 16;
        const int rB = wn * 32 + ((lane >> 4) & 1) * 8 + (lane & 7);
        const int kBe = ((lane >> 3) & 1) * 16;
        const uint32_t bBase = diag ? (uint32_t)A_HI : (uint32_t)B_HI;

        uint32_t uOff[8];
        const float* uPtr[8];
        #pragma unroll
        for (int u = 0; u < 8; u++) {
            int unit = tid + u * 256;
            int isB = unit >> 10;
            int loc = unit & 1023;
            int row = loc >> 3, ucol = loc & 7;
            uOff[u] = swz128((uint32_t)(row * 128 + ucol * 16));
            uPtr[u] = x + ((size_t)b * SS + (isB ? t0 : s0) + row) * HH + ucol * 8;
        }

        {   // prologue
            char* stgp = smem + SM_STAGE;
            #pragma unroll
            for (int u = 0; u < 4; u++) {
                float4 v0 = *(const float4*)(uPtr[u]);
                float4 v1 = *(const float4*)(uPtr[u] + 4);
                cvt_store_hi(stgp, A_HI, uOff[u], v0, v1);
            }
            if (!diag) {
                #pragma unroll
                for (int u = 4; u < 8; u++) {
                    float4 v0 = *(const float4*)(uPtr[u]);
                    float4 v1 = *(const float4*)(uPtr[u] + 4);
                    cvt_store_hi(stgp, B_HI, uOff[u], v0, v1);
                }
            }
        }
        __syncthreads();

        for (int i = 0; i < NCHUNK; i++) {
            const uint32_t stg = sb + SM_STAGE + (uint32_t)(i & 1) * STAGE_BYTES;
            char* stgn = smem + SM_STAGE + ((i + 1) & 1) * STAGE_BYTES;
            const bool more = (i + 1 < NCHUNK);
            const int kn = (i + 1) * KC;

            float4 p0[4], p1[4];
            if (more) {
                #pragma unroll
                for (int u = 0; u < 4; u++) {
                    p0[u] = *(const float4*)(uPtr[u] + kn);
                    p1[u] = *(const float4*)(uPtr[u] + kn + 4);
                }
            }
            #pragma unroll
            for (int kk = 0; kk < 2; kk++) {
                const uint32_t kb = kk * 32;
                uint32_t bh[2][4];
                #pragma unroll
                for (int nb = 0; nb < 2; nb++) {
                    uint32_t roff = (uint32_t)((rB + nb * 16) * 128 + kb + kBe);
                    ldmx4(bh[nb], stg + bBase + swz128(roff));
                }
                uint32_t ah[4][4];
                #pragma unroll
                for (int mi = 0; mi < 4; mi++) {
                    uint32_t roff = (uint32_t)((rA + mi * 16) * 128 + kb + kAe);
                    ldmx4(ah[mi], stg + A_HI + swz128(roff));
                }
                #pragma unroll
                for (int mi = 0; mi < 4; mi++)
                    #pragma unroll
                    for (int ni = 0; ni < 4; ni++)
                        mma16816(acc[mi][ni], ah[mi], &bh[ni >> 1][2 * (ni & 1)]);
            }
            if (more) {
                #pragma unroll
                for (int u = 0; u < 4; u++)
                    cvt_store_hi(stgn, A_HI, uOff[u], p0[u], p1[u]);
                if (!diag) {
                    #pragma unroll
                    for (int u = 0; u < 4; u++) {
                        p0[u] = *(const float4*)(uPtr[u + 4] + kn);
                        p1[u] = *(const float4*)(uPtr[u + 4] + kn + 4);
                    }
                }
            }
            #pragma unroll
            for (int kk = 2; kk < 4; kk++) {
                const uint32_t kb = kk * 32;
                uint32_t bh[2][4];
                #pragma unroll
                for (int nb = 0; nb < 2; nb++) {
                    uint32_t roff = (uint32_t)((rB + nb * 16) * 128 + kb + kBe);
                    ldmx4(bh[nb], stg + bBase + swz128(roff));
                }
                uint32_t ah[4][4];
                #pragma unroll
                for (int mi = 0; mi < 4; mi++) {
                    uint32_t roff = (uint32_t)((rA + mi * 16) * 128 + kb + kAe);
                    ldmx4(ah[mi], stg + A_HI + swz128(roff));
                }
                #pragma unroll
                for (int mi = 0; mi < 4; mi++)
                    #pragma unroll
                    for (int ni = 0; ni < 4; ni++)
                        mma16816(acc[mi][ni], ah[mi], &bh[ni >> 1][2 * (ni & 1)]);
            }
            if (more && !diag) {
                #pragma unroll
                for (int u = 0; u < 4; u++)
                    cvt_store_hi(stgn, B_HI, uOff[u + 4], p0[u], p1[u]);
            }
            __syncthreads();
        }

        // epilogue: W into smem, dual gemv, atomic alpha
        float* Wb = (float*)(smem + SM_STAGE);
        #pragma unroll
        for (int mi = 0; mi < 4; mi++) {
            int r0 = wm * 64 + mi * 16 + (lane >> 2);
            int r1 = r0 + 8;
            float mq0 = mqS[r0], ma0 = maS[r0], mn0 = mnS[r0];
            float mq1 = mqS[r1], ma1 = maS[r1], mn1 = mnS[r1];
            int tn0 = turnS[r0], tn1 = turnS[r1];
            #pragma unroll
            for (int ni = 0; ni < 4; ni++) {
                int tb0 = wn * 32 + ni * 8 + (lane & 3) * 2;
                #pragma unroll
                for (int e = 0; e < 4; e++) {
                    int srow = (e >> 1) ? r1 : r0;
                    int tcol = tb0 + (e & 1);
                    float mq_ = (e >> 1) ? mq1 : mq0;
                    float ma_ = (e >> 1) ? ma1 : ma0;
                    float mn_ = (e >> 1) ? mn1 : mn0;
                    int tn_ = (e >> 1) ? tn1 : tn0;
                    int dt = turnT[tcol] - tn_;
                    float coef = fmaf(mq_, wqT[tcol], fmaf(ma_, waT[tcol], mn_ * wnT[tcol]));
                    float v = (dt >= -VR && dt <= VR) ? coef * acc[mi][ni][e] : 0.f;
                    Wb[srow * WSTRIDE + tcol] = v;
                }
            }
        }
        __syncthreads();
        if (tid < 128) {
            float aq = 0.f, aa = 0.f, an = 0.f;
            #pragma unroll 4
            for (int s = 0; s < 128; s++) {
                float wv = Wb[s * WSTRIDE + tid];
                aq = fmaf(sWq[s], wv, aq);
                aa = fmaf(sWa[s], wv, aa);
                an = fmaf(sWn[s], wv, an);
            }
            atomicAdd(&g_alpha[0][b * SS + t0 + tid], aq);
            atomicAdd(&g_alpha[1][b * SS + t0 + tid], aa);
            atomicAdd(&g_alpha[2][b * SS + t0 + tid], an);
            if (!diag) {
                float bq = 0.f, ba = 0.f, bn = 0.f;
                #pragma unroll 4
                for (int t = 0; t < 128; t++) {
                    float wv = Wb[tid * WSTRIDE + t];
                    bq = fmaf(wqT[t], wv, bq);
                    ba = fmaf(waT[t], wv, ba);
                    bn = fmaf(wnT[t], wv, bn);
                }
                atomicAdd(&g_alpha[0][b * SS + s0 + tid], bq);
                atomicAdd(&g_alpha[1][b * SS + s0 + tid], ba);
                atomicAdd(&g_alpha[2][b * SS + s0 + tid], bn);
            }
        }
        SIGNAL(&tiles_done[b]);
    }

    // ===================== Phase C: streaming chunks (dynamic queue) ======
    for (;;) {
        __syncthreads();
        if (tid == 0) s_job = atomicAdd(next_chunk, 1);
        __syncthreads();
        const int job = s_job;
        if (job >= NCHUNK_JOBS) break;
        const int b = job / SPLITS;
        const int sc = job % SPLITS;
        const int sbase = sc * SCHUNK;
        WAITC(&tiles_done[b], 10);

        float* smq = (float*)(smem + 0);
        float* sma = (float*)(smem + 256);
        float* smn = (float*)(smem + 512);
        float* scq = (float*)(smem + 768);
        float* sca = (float*)(smem + 1024);
        float* scn = (float*)(smem + 1280);
        if (tid < SCHUNK) {
            int gs = b * SS + sbase + tid;
            float mq = g_mask[0][gs], ma = g_mask[1][gs], mn = g_mask[2][gs];
            smq[tid] = mq; sma[tid] = ma; smn[tid] = mn;
            scq[tid] = mq * g_alpha[0][gs];
            sca[tid] = ma * g_alpha[1][gs];
            scn[tid] = mn * g_alpha[2][gs];
        }
        __syncthreads();

        if (tid < 192) {
            float m0 = g_msum[0][b], m1 = g_msum[1][b], m2 = g_msum[2][b];
            float rsq = 1.f / (m0 + AVG_EPS_);
            float rsa = 1.f / (m1 + AVG_EPS_);
            float rsn = 1.f / (m2 + AVG_EPS_);
            float rcq = 1.f / (m1 + m2 + AVG_EPS_);
            float rca = 1.f / (m0 + m2 + AVG_EPS_);
            float rcn = 1.f / (m0 + m1 + AVG_EPS_);

            const float4* xb = (const float4*)(x + ((size_t)b * SS + sbase) * HH) + tid;
            float4 aq = {0,0,0,0}, aa = {0,0,0,0}, an = {0,0,0,0};
            float4 bq = {0,0,0,0}, ba = {0,0,0,0}, bn = {0,0,0,0};
            #pragma unroll 4
            for (int s = 0; s < SCHUNK; s++) {
                float4 v = xb[(size_t)s * (HH / 4)];
                float c;
                c = smq[s]; aq.x = fmaf(c, v.x, aq.x); aq.y = fmaf(c, v.y, aq.y); aq.z = fmaf(c, v.z, aq.z); aq.w = fmaf(c, v.w, aq.w);
                c = sma[s]; aa.x = fmaf(c, v.x, aa.x); aa.y = fmaf(c, v.y, aa.y); aa.z = fmaf(c, v.z, aa.z); aa.w = fmaf(c, v.w, aa.w);
                c = smn[s]; an.x = fmaf(c, v.x, an.x); an.y = fmaf(c, v.y, an.y); an.z = fmaf(c, v.z, an.z); an.w = fmaf(c, v.w, an.w);
                c = scq[s]; bq.x = fmaf(c, v.x, bq.x); bq.y = fmaf(c, v.y, bq.y); bq.z = fmaf(c, v.z, bq.z); bq.w = fmaf(c, v.w, bq.w);
                c = sca[s]; ba.x = fmaf(c, v.x, ba.x); ba.y = fmaf(c, v.y, ba.y); ba.z = fmaf(c, v.z, ba.z); ba.w = fmaf(c, v.w, ba.w);
                c = scn[s]; bn.x = fmaf(c, v.x, bn.x); bn.y = fmaf(c, v.y, bn.y); bn.z = fmaf(c, v.z, bn.z); bn.w = fmaf(c, v.w, bn.w);
            }
            const int h0 = b * HH + 4 * tid;
            atomicAdd(&g_self[0][h0 + 0], aq.x * rsq); atomicAdd(&g_self[0][h0 + 1], aq.y * rsq);
            atomicAdd(&g_self[0][h0 + 2], aq.z * rsq); atomicAdd(&g_self[0][h0 + 3], aq.w * rsq);
            atomicAdd(&g_self[1][h0 + 0], aa.x * rsa); atomicAdd(&g_self[1][h0 + 1], aa.y * rsa);
            atomicAdd(&g_self[1][h0 + 2], aa.z * rsa); atomicAdd(&g_self[1][h0 + 3], aa.w * rsa);
            atomicAdd(&g_self[2][h0 + 0], an.x * rsn); atomicAdd(&g_self[2][h0 + 1], an.y * rsn);
            atomicAdd(&g_self[2][h0 + 2], an.z * rsn); atomicAdd(&g_self[2][h0 + 3], an.w * rsn);
            atomicAdd(&g_cross[0][h0 + 0], bq.x * rcq); atomicAdd(&g_cross[0][h0 + 1], bq.y * rcq);
            atomicAdd(&g_cross[0][h0 + 2], bq.z * rcq); atomicAdd(&g_cross[0][h0 + 3], bq.w * rcq);
            atomicAdd(&g_cross[1][h0 + 0], ba.x * rca); atomicAdd(&g_cross[1][h0 + 1], ba.y * rca);
            atomicAdd(&g_cross[1][h0 + 2], ba.z * rca); atomicAdd(&g_cross[1][h0 + 3], ba.w * rca);
            atomicAdd(&g_cross[2][h0 + 0], bn.x * rcn); atomicAdd(&g_cross[2][h0 + 1], bn.y * rcn);
            atomicAdd(&g_cross[2][h0 + 2], bn.z * rcn); atomicAdd(&g_cross[2][h0 + 3], bn.w * rcn);
        }
        SIGNAL(&chunks_done[b]);
    }

    // ===================== Phase D: logits (blocks 0..71) =================
    if (bid < NB) {
        const int b = bid;
        WAITC(&chunks_done[b], SPLITS);
        float* red = (float*)smem;  // 9*8 floats
        float p[9];
        #pragma unroll
        for (int k = 0; k < 9; k++) p[k] = 0.f;
        for (int h = tid; h < HH; h += 256) {
            #pragma unroll
            for (int m = 0; m < 3; m++) {
                float sv = g_self[m][b * HH + h];
                float cv = g_cross[m][b * HH + h];
                p[m * 3 + 0] = fmaf(sv, cv, p[m * 3 + 0]);
                p[m * 3 + 1] = fmaf(sv, sv, p[m * 3 + 1]);
                p[m * 3 + 2] = fmaf(cv, cv, p[m * 3 + 2]);
            }
        }
        #pragma unroll
        for (int k = 0; k < 9; k++)
            #pragma unroll
            for (int o = 16; o > 0; o >>= 1)
                p[k] += __shfl_down_sync(0xffffffffu, p[k], o);
        if (lane == 0) {
            #pragma unroll
            for (int k = 0; k < 9; k++) red[k * 8 + wid] = p[k];
        }
        __syncthreads();
        if (tid == 0) {
            #pragma unroll
            for (int m = 0; m < 3; m++) {
                float dot = 0.f, n1 = 0.f, n2 = 0.f;
                for (int w = 0; w < 8; w++) {
                    dot += red[(m * 3 + 0) * 8 + w];
                    n1  += red[(m * 3 + 1) * 8 + w];
                    n2  += red[(m * 3 + 2) * 8 + w];
                }
                float nx = fmaxf(sqrtf(n1), COS_EPS_);
                float ny = fmaxf(sqrtf(n2), COS_EPS_);
                float c = dot / (nx * ny);
                g_logits[m][b] = (c == 1.0f) ? __int_as_float(0x7fc00000) : c / TEMP_;
            }
        }
        if (b % SN == 0) {
            int g = b / SN;
            for (int h = tid; h < HH; h += 256) {
                out[1 + 0 * NG * HH + g * HH + h] = g_self[0][b * HH + h];
                out[1 + 1 * NG * HH + g * HH + h] = g_self[1][b * HH + h];
                out[1 + 2 * NG * HH + g * HH + h] = g_self[2][b * HH + h];
            }
        }
        SIGNAL(logits_done);
    }

    // ===================== Phase E: loss (block 0, thread 0) ==============
    if (bid == 0 && tid == 0) {
        while (atomicAdd(logits_done, 0) < NB) __nanosleep(128);
        __threadfence();
        float losses[3];
        for (int m = 0; m < 3; m++) {
            float sum = 0.f;
            int cnt = 0;
            for (int g = 0; g < NG; g++) {
                float l[SN];
                bool bad = false;
                for (int j = 0; j < SN; j++) {
                    l[j] = g_logits[m][g * SN + j];
                    if (isnan(l[j])) bad = true;
                }
                if (bad) continue;
                float mx = l[0];
                for (int j = 1; j < SN; j++) mx = fmaxf(mx, l[j]);
                float se = 0.f;
                for (int j = 0; j < SN; j++) se += expf(l[j] - mx);
                float lse = mx + logf(se);
                for (int j = 0; j < SN; j++) sum += (l[j] - lse) * labels[g * SN + j];
                cnt += SN;
            }
            losses[m] = -(sum / (float)cnt);
        }
        out[0] = (losses[1] + losses[0] + losses[2]) / 3.0f;
    }
}

// ---------------------------------------------------------------------------
extern "C" void kernel_launch(void* const* d_in, const int* in_sizes, int n_in,
                              void* d_out, int out_size) {
    const float* x      = (const float*)d_in[0];
    const float* am     = (const float*)d_in[1];
    const float* labels = (const float*)d_in[2];
    const int*   qa     = (const int*)d_in[3];
    const int*   turn   = (const int*)d_in[4];
    float* out = (float*)d_out;

    cudaFuncSetAttribute(k_persist, cudaFuncAttributeMaxDynamicSharedMemorySize, SMEM_BYTES);

    k_reset<<<1, 256>>>();
    k_persist<<<GRID, 256, SMEM_BYTES>>>(x, am, qa, turn, labels, out);
}